// round 2
// baseline (speedup 1.0000x reference)
#include <cuda_runtime.h>

#define HID 1024
#define HEADS 16
#define HD 64
#define BATCH 8
#define SEQ 1024
#define MROWS (BATCH * SEQ)

// -------- scratch (static device globals; no allocations allowed) --------
__device__ float g_Q[MROWS * HID];
__device__ float g_K[MROWS * HID];
__device__ float g_V[MROWS * HID];
__device__ float g_C[MROWS * HID];
__device__ float g_invf[HID / 2];

// -------- packed f32x2 helpers (FFMA2 path: 2x scalar-FFMA throughput) --------
__device__ __forceinline__ unsigned long long f2pack(float lo, float hi) {
    unsigned long long r;
    asm("mov.b64 %0, {%1, %2};" : "=l"(r) : "f"(lo), "f"(hi));
    return r;
}
__device__ __forceinline__ void f2fma(unsigned long long& d,
                                      unsigned long long a,
                                      unsigned long long b) {
    asm("fma.rn.f32x2 %0, %1, %2, %0;" : "+l"(d) : "l"(a), "l"(b));
}
__device__ __forceinline__ void f2mul(unsigned long long& d,
                                      unsigned long long a,
                                      unsigned long long b) {
    asm("mul.rn.f32x2 %0, %1, %2;" : "=l"(d) : "l"(a), "l"(b));
}
__device__ __forceinline__ void f2add(unsigned long long& d,
                                      unsigned long long a,
                                      unsigned long long b) {
    asm("add.rn.f32x2 %0, %1, %2;" : "=l"(d) : "l"(a), "l"(b));
}
__device__ __forceinline__ float2 f2unpack(unsigned long long v) {
    float2 r;
    asm("mov.b64 {%0, %1}, %2;" : "=f"(r.x), "=f"(r.y) : "l"(v));
    return r;
}

// ============================================================================
// GEMM (NT):  Y[m,n] = sum_k X[m,k] * W[n,k] + bias[n]
// M = 8192, N = K = 1024. Tile 128x128x16, 256 threads, 8x8 per thread
// as four 4x4 quadrants. Inner loop in fma.rn.f32x2.
// ============================================================================
__global__ __launch_bounds__(256) void gemm_nt_bias(
    const float* __restrict__ X, const float* __restrict__ W,
    const float* __restrict__ bias, float* __restrict__ Y)
{
    __shared__ float As[16][128];
    __shared__ float Bs[16][128];

    const int tid  = threadIdx.x;
    const int brow = blockIdx.y * 128;
    const int bcol = blockIdx.x * 128;
    const int tx   = tid & 15;
    const int ty   = tid >> 4;

    unsigned long long acc[8][4];
#pragma unroll
    for (int i = 0; i < 8; i++)
#pragma unroll
        for (int j = 0; j < 4; j++) acc[i][j] = 0ULL;

    // global-load mapping: 128 rows x 16 cols = 512 float4; 2 per thread
    const int lr1 = tid >> 2;          // rows 0..63
    const int lr2 = lr1 + 64;          // rows 64..127
    const int lc4 = (tid & 3) * 4;     // col within 16-wide k-slab

    const float* Xp = X + (size_t)brow * HID;
    const float* Wp = W + (size_t)bcol * HID;

    for (int k0 = 0; k0 < HID; k0 += 16) {
        float4 a1v = *(const float4*)(Xp + (size_t)lr1 * HID + k0 + lc4);
        float4 a2v = *(const float4*)(Xp + (size_t)lr2 * HID + k0 + lc4);
        float4 b1v = *(const float4*)(Wp + (size_t)lr1 * HID + k0 + lc4);
        float4 b2v = *(const float4*)(Wp + (size_t)lr2 * HID + k0 + lc4);

        __syncthreads();
        As[lc4 + 0][lr1] = a1v.x; As[lc4 + 1][lr1] = a1v.y;
        As[lc4 + 2][lr1] = a1v.z; As[lc4 + 3][lr1] = a1v.w;
        As[lc4 + 0][lr2] = a2v.x; As[lc4 + 1][lr2] = a2v.y;
        As[lc4 + 2][lr2] = a2v.z; As[lc4 + 3][lr2] = a2v.w;
        Bs[lc4 + 0][lr1] = b1v.x; Bs[lc4 + 1][lr1] = b1v.y;
        Bs[lc4 + 2][lr1] = b1v.z; Bs[lc4 + 3][lr1] = b1v.w;
        Bs[lc4 + 0][lr2] = b2v.x; Bs[lc4 + 1][lr2] = b2v.y;
        Bs[lc4 + 2][lr2] = b2v.z; Bs[lc4 + 3][lr2] = b2v.w;
        __syncthreads();

#pragma unroll
        for (int kk = 0; kk < 16; kk++) {
            float4 a0 = *(const float4*)&As[kk][ty * 4];
            float4 a1 = *(const float4*)&As[kk][ty * 4 + 64];
            ulonglong2 b0 = *(const ulonglong2*)&Bs[kk][tx * 4];
            ulonglong2 b1 = *(const ulonglong2*)&Bs[kk][tx * 4 + 64];

            unsigned long long av[8];
            av[0] = f2pack(a0.x, a0.x); av[1] = f2pack(a0.y, a0.y);
            av[2] = f2pack(a0.z, a0.z); av[3] = f2pack(a0.w, a0.w);
            av[4] = f2pack(a1.x, a1.x); av[5] = f2pack(a1.y, a1.y);
            av[6] = f2pack(a1.z, a1.z); av[7] = f2pack(a1.w, a1.w);

#pragma unroll
            for (int i = 0; i < 8; i++) {
                f2fma(acc[i][0], av[i], b0.x);
                f2fma(acc[i][1], av[i], b0.y);
                f2fma(acc[i][2], av[i], b1.x);
                f2fma(acc[i][3], av[i], b1.y);
            }
        }
    }

    float4 bl0 = *(const float4*)(bias + bcol + tx * 4);
    float4 bl1 = *(const float4*)(bias + bcol + tx * 4 + 64);

#pragma unroll
    for (int i = 0; i < 8; i++) {
        int row = brow + ((i < 4) ? (ty * 4 + i) : (64 + ty * 4 + (i - 4)));
        float2 c0 = f2unpack(acc[i][0]);
        float2 c1 = f2unpack(acc[i][1]);
        float2 c2 = f2unpack(acc[i][2]);
        float2 c3 = f2unpack(acc[i][3]);
        float4 o0 = make_float4(c0.x + bl0.x, c0.y + bl0.y, c1.x + bl0.z, c1.y + bl0.w);
        float4 o1 = make_float4(c2.x + bl1.x, c2.y + bl1.y, c3.x + bl1.z, c3.y + bl1.w);
        *(float4*)(Y + (size_t)row * HID + bcol + tx * 4)      = o0;
        *(float4*)(Y + (size_t)row * HID + bcol + tx * 4 + 64) = o1;
    }
}

// ============================================================================
// RoPE table (double precision to match JAX fp32 table to ~ulp) + apply.
// Reference quirk reproduced: pos_emb = [sin(t), cos(t)], then apply takes
// cos/sin OF those values, and V is roped too.
// ============================================================================
__global__ void make_invf_kernel() {
    int j = threadIdx.x;
    if (j < HID / 2) {
        double e = exp(-((double)(2 * j) / (double)HID) * log(10000.0));
        g_invf[j] = (float)e;
    }
}

__global__ __launch_bounds__(256) void rope_apply_kernel() {
    int idx = blockIdx.x * 256 + threadIdx.x;       // MROWS * 512 threads
    int row = idx >> 9;
    int j   = idx & 511;
    int s   = row & (SEQ - 1);

    float t = (float)s * g_invf[j];
    float st, ct;
    sincosf(t, &st, &ct);
    float s1, c1, s2, c2;
    sincosf(st, &s1, &c1);   // sin(sin t), cos(sin t)
    sincosf(ct, &s2, &c2);   // sin(cos t), cos(cos t)

    size_t i1 = (size_t)row * HID + j;
    size_t i2 = i1 + 512;

    {
        float x1 = g_Q[i1], x2 = g_Q[i2];
        g_Q[i1] = x1 * c1 + x2 * s1;
        g_Q[i2] = x2 * c2 - x1 * s2;
    }
    {
        float x1 = g_K[i1], x2 = g_K[i2];
        g_K[i1] = x1 * c1 + x2 * s1;
        g_K[i2] = x2 * c2 - x1 * s2;
    }
    {
        float x1 = g_V[i1], x2 = g_V[i2];
        g_V[i1] = x1 * c1 + x2 * s1;
        g_V[i2] = x2 * c2 - x1 * s2;
    }
}

// ============================================================================
// Flash-style attention. Grid (16 q-tiles, 128 b*h), 64 threads/block,
// one thread per query row. Q and O accumulators in packed f32x2 registers,
// K/V tiles in smem (broadcast reads), scores parked in Ss[kk][tid]
// (conflict-free). Online softmax, scale = 1/sqrt(64) = 0.125.
// ============================================================================
__global__ __launch_bounds__(64) void attn_kernel() {
    __shared__ float Ks[64][64];
    __shared__ float Vs[64][64];
    __shared__ float Ss[64][64];   // [key][thread]

    const int tid = threadIdx.x;
    const int qt  = blockIdx.x;
    const int bh  = blockIdx.y;
    const int b   = bh >> 4;
    const int h   = bh & 15;
    const int base_row = b * SEQ;
    const int qrow = base_row + qt * 64 + tid;

    const float* qptr = g_Q + (size_t)qrow * HID + h * HD;

    unsigned long long q2[32];
#pragma unroll
    for (int i = 0; i < 16; i++) {
        ulonglong2 v = ((const ulonglong2*)qptr)[i];
        q2[2 * i] = v.x; q2[2 * i + 1] = v.y;
    }
    unsigned long long o2[32];
#pragma unroll
    for (int i = 0; i < 32; i++) o2[i] = 0ULL;

    float m = -1e30f, l = 0.0f;

    for (int kt = 0; kt < 16; kt++) {
        __syncthreads();
        const float* kbase = g_K + (size_t)(base_row + kt * 64) * HID + h * HD;
        const float* vbase = g_V + (size_t)(base_row + kt * 64) * HID + h * HD;
#pragma unroll
        for (int i = 0; i < 16; i++) {
            int idx = i * 64 + tid;
            int rr = idx >> 4, c4 = idx & 15;
            ((float4*)Ks)[idx] = *(const float4*)(kbase + (size_t)rr * HID + c4 * 4);
            ((float4*)Vs)[idx] = *(const float4*)(vbase + (size_t)rr * HID + c4 * 4);
        }
        __syncthreads();

        // pass 1: scores + tile max
        float tmax = -1e30f;
#pragma unroll 4
        for (int kk = 0; kk < 64; kk++) {
            const ulonglong2* kp = (const ulonglong2*)&Ks[kk][0];
            unsigned long long sa = 0ULL, sb = 0ULL, sc = 0ULL, sd = 0ULL;
#pragma unroll
            for (int i = 0; i < 8; i++) {
                ulonglong2 k0 = kp[2 * i];
                ulonglong2 k1 = kp[2 * i + 1];
                f2fma(sa, q2[4 * i + 0], k0.x);
                f2fma(sb, q2[4 * i + 1], k0.y);
                f2fma(sc, q2[4 * i + 2], k1.x);
                f2fma(sd, q2[4 * i + 3], k1.y);
            }
            f2add(sa, sa, sb);
            f2add(sc, sc, sd);
            f2add(sa, sa, sc);
            float2 sv = f2unpack(sa);
            float sval = (sv.x + sv.y) * 0.125f;
            Ss[kk][tid] = sval;
            tmax = fmaxf(tmax, sval);
        }

        // online softmax rescale
        float mnew = fmaxf(m, tmax);
        float corr = __expf(m - mnew);
        l *= corr;
        unsigned long long corr2 = f2pack(corr, corr);
#pragma unroll
        for (int i = 0; i < 32; i++) f2mul(o2[i], o2[i], corr2);

        // pass 2: p = exp(s - mnew); O += p * V
#pragma unroll 2
        for (int kk = 0; kk < 64; kk++) {
            float p = __expf(Ss[kk][tid] - mnew);
            l += p;
            unsigned long long p2 = f2pack(p, p);
            const ulonglong2* vp = (const ulonglong2*)&Vs[kk][0];
#pragma unroll
            for (int i = 0; i < 16; i++) {
                ulonglong2 vv = vp[i];
                f2fma(o2[2 * i],     p2, vv.x);
                f2fma(o2[2 * i + 1], p2, vv.y);
            }
        }
        m = mnew;
    }

    float inv = 1.0f / l;
    unsigned long long inv2 = f2pack(inv, inv);
    float* cptr = g_C + (size_t)qrow * HID + h * HD;
#pragma unroll
    for (int i = 0; i < 32; i++) f2mul(o2[i], o2[i], inv2);
#pragma unroll
    for (int i = 0; i < 16; i++) {
        ulonglong2 v;
        v.x = o2[2 * i]; v.y = o2[2 * i + 1];
        ((ulonglong2*)cptr)[i] = v;
    }
}

// ============================================================================
// launch
// ============================================================================
extern "C" void kernel_launch(void* const* d_in, const int* in_sizes, int n_in,
                              void* d_out, int out_size) {
    (void)in_sizes; (void)n_in; (void)out_size;
    const float* query = (const float*)d_in[0];
    const float* key   = (const float*)d_in[1];
    const float* value = (const float*)d_in[2];
    const float* Wq    = (const float*)d_in[3];
    const float* bq    = (const float*)d_in[4];
    const float* Wk    = (const float*)d_in[5];
    const float* bk    = (const float*)d_in[6];
    const float* Wv    = (const float*)d_in[7];
    const float* bv    = (const float*)d_in[8];
    const float* Wo    = (const float*)d_in[9];
    const float* bo    = (const float*)d_in[10];
    float* out = (float*)d_out;

    float *Qp, *Kp, *Vp, *Cp;
    cudaGetSymbolAddress((void**)&Qp, g_Q);
    cudaGetSymbolAddress((void**)&Kp, g_K);
    cudaGetSymbolAddress((void**)&Vp, g_V);
    cudaGetSymbolAddress((void**)&Cp, g_C);

    dim3 ggrid(HID / 128, MROWS / 128);   // (8, 64)

    make_invf_kernel<<<1, 512>>>();
    gemm_nt_bias<<<ggrid, 256>>>(query, Wq, bq, Qp);
    gemm_nt_bias<<<ggrid, 256>>>(key,   Wk, bk, Kp);
    gemm_nt_bias<<<ggrid, 256>>>(value, Wv, bv, Vp);
    rope_apply_kernel<<<(MROWS * 512) / 256, 256>>>();
    attn_kernel<<<dim3(16, 128), 64>>>();
    gemm_nt_bias<<<ggrid, 256>>>(Cp, Wo, bo, out);
}

// round 4
// speedup vs baseline: 1.4877x; 1.4877x over previous
#include <cuda_runtime.h>
#include <cuda_bf16.h>
#include <cstdint>

#define HID 1024
#define HEADS 16
#define HD 64
#define BATCH 8
#define SEQ 1024
#define MROWS (BATCH * SEQ)

// ---------------- scratch (device globals; no allocation allowed) ----------
__device__ float g_Q[MROWS * HID];
__device__ float g_K[MROWS * HID];
__device__ float g_V[MROWS * HID];
__device__ __nv_bfloat16 g_Ahi[MROWS * HID];
__device__ __nv_bfloat16 g_Alo[MROWS * HID];
__device__ __nv_bfloat16 g_Bhi[HID * HID];
__device__ __nv_bfloat16 g_Blo[HID * HID];
__device__ float g_invf[HID / 2];
__device__ float4 g_tab[SEQ * (HID / 2)];

// ---------------- helpers ----------------------------------------
__device__ __forceinline__ uint32_t smem_u32(const void* p) {
    uint32_t a;
    asm("{ .reg .u64 t; cvta.to.shared.u64 t, %1; cvt.u32.u64 %0, t; }"
        : "=r"(a) : "l"(p));
    return a;
}
__device__ __forceinline__ void ldm4(uint32_t* r, uint32_t addr) {
    asm volatile("ldmatrix.sync.aligned.m8n8.x4.shared.b16 {%0,%1,%2,%3}, [%4];"
                 : "=r"(r[0]), "=r"(r[1]), "=r"(r[2]), "=r"(r[3]) : "r"(addr));
}
__device__ __forceinline__ void mma16816(float* d, const uint32_t* a,
                                         uint32_t b0, uint32_t b1) {
    asm volatile(
        "mma.sync.aligned.m16n8k16.row.col.f32.bf16.bf16.f32 "
        "{%0,%1,%2,%3}, {%4,%5,%6,%7}, {%8,%9}, {%0,%1,%2,%3};"
        : "+f"(d[0]), "+f"(d[1]), "+f"(d[2]), "+f"(d[3])
        : "r"(a[0]), "r"(a[1]), "r"(a[2]), "r"(a[3]), "r"(b0), "r"(b1));
}

// ---------------- packed f32x2 helpers (attention) --------------------------
__device__ __forceinline__ unsigned long long f2pack(float lo, float hi) {
    unsigned long long r;
    asm("mov.b64 %0, {%1, %2};" : "=l"(r) : "f"(lo), "f"(hi));
    return r;
}
__device__ __forceinline__ void f2fma(unsigned long long& d, unsigned long long a,
                                      unsigned long long b) {
    asm("fma.rn.f32x2 %0, %1, %2, %0;" : "+l"(d) : "l"(a), "l"(b));
}
__device__ __forceinline__ void f2mul(unsigned long long& d, unsigned long long a,
                                      unsigned long long b) {
    asm("mul.rn.f32x2 %0, %1, %2;" : "=l"(d) : "l"(a), "l"(b));
}
__device__ __forceinline__ void f2add(unsigned long long& d, unsigned long long a,
                                      unsigned long long b) {
    asm("add.rn.f32x2 %0, %1, %2;" : "=l"(d) : "l"(a), "l"(b));
}
__device__ __forceinline__ float2 f2unpack(unsigned long long v) {
    float2 r;
    asm("mov.b64 {%0, %1}, %2;" : "=f"(r.x), "=f"(r.y) : "l"(v));
    return r;
}

// ============================================================================
// fp32 -> bf16 split (hi + lo). n4 = elements/4.
// ============================================================================
__global__ __launch_bounds__(256) void split_bf16_kernel(
    const float* __restrict__ src, __nv_bfloat16* __restrict__ hi,
    __nv_bfloat16* __restrict__ lo, int n4)
{
    int idx = blockIdx.x * 256 + threadIdx.x;
    if (idx >= n4) return;
    float4 v = ((const float4*)src)[idx];
    __nv_bfloat162 h01 = __floats2bfloat162_rn(v.x, v.y);
    __nv_bfloat162 h23 = __floats2bfloat162_rn(v.z, v.w);
    float2 f01 = __bfloat1622float2(h01);
    float2 f23 = __bfloat1622float2(h23);
    __nv_bfloat162 l01 = __floats2bfloat162_rn(v.x - f01.x, v.y - f01.y);
    __nv_bfloat162 l23 = __floats2bfloat162_rn(v.z - f23.x, v.w - f23.y);
    ((__nv_bfloat162*)hi)[2 * idx]     = h01;
    ((__nv_bfloat162*)hi)[2 * idx + 1] = h23;
    ((__nv_bfloat162*)lo)[2 * idx]     = l01;
    ((__nv_bfloat162*)lo)[2 * idx + 1] = l23;
}

// ============================================================================
// mma.sync bf16 GEMM (NT): Y[m,n] = sum_k X[m,k]*W[n,k] + bias[n]
// 3-term split emulation (hh + hl + lh). CTA tile 128x128, warp tile 64x32,
// K-chunk 32, double-buffered smem with 80B row stride (conflict-free ldmatrix).
// ============================================================================
#define RSTRIDE 80
#define TILE_B (128 * RSTRIDE)      // 10240
#define STAGE_B (4 * TILE_B)        // 40960 (Ahi, Alo, Bhi, Blo)
#define GEMM_SMEM (2 * STAGE_B)     // 81920

__global__ __launch_bounds__(256, 1)
void gemm_mma(const __nv_bfloat16* __restrict__ Ahi, const __nv_bfloat16* __restrict__ Alo,
              const __nv_bfloat16* __restrict__ Bhi, const __nv_bfloat16* __restrict__ Blo,
              const float* __restrict__ bias, float* __restrict__ Y)
{
    extern __shared__ __align__(128) char smem[];

    const int tid  = threadIdx.x;
    const int wid  = tid >> 5;
    const int lane = tid & 31;
    const int wm   = wid & 1;          // 2 warps along M
    const int wn   = wid >> 1;         // 4 warps along N
    const int brow = blockIdx.y * 128;
    const int bcol = blockIdx.x * 128;

    const uint32_t sbase = smem_u32(smem);

    // ldmatrix per-lane offsets within a tile
    // A: r0=(m0-7,k0-7) r1=(m8-15,k0-7) r2=(m0-7,k8-15) r3=(m8-15,k8-15)
    const uint32_t aoff = (uint32_t)(((lane & 7) + ((lane >> 3) & 1) * 8) * RSTRIDE
                                     + ((lane >> 4) & 1) * 16);
    // B: r0=(n0-7,k0-7) r1=(n0-7,k8-15) r2=(n8-15,k0-7) r3=(n8-15,k8-15)
    const uint32_t boff = (uint32_t)(((lane & 7) + ((lane >> 4) & 1) * 8) * RSTRIDE
                                     + ((lane >> 3) & 1) * 16);

    // global load mapping: per tile 512 uint4 (128 rows x 4 chunks of 16B)
    const int r0i = tid >> 2;          // rows r0i and r0i+64
    const int ch  = tid & 3;

    const __nv_bfloat16* gptr[4];
    gptr[0] = Ahi + (size_t)brow * HID;
    gptr[1] = Alo + (size_t)brow * HID;
    gptr[2] = Bhi + (size_t)bcol * HID;
    gptr[3] = Blo + (size_t)bcol * HID;

    float acc[4][4][4];
#pragma unroll
    for (int i = 0; i < 4; i++)
#pragma unroll
        for (int j = 0; j < 4; j++)
#pragma unroll
            for (int r = 0; r < 4; r++) acc[i][j][r] = 0.0f;

    // prologue: chunk 0 -> stage 0
    {
        const size_t koff = (size_t)ch * 8;
#pragma unroll
        for (int t = 0; t < 4; t++) {
            uint4 v0 = *(const uint4*)(gptr[t] + (size_t)r0i * HID + koff);
            uint4 v1 = *(const uint4*)(gptr[t] + (size_t)(r0i + 64) * HID + koff);
            *(uint4*)(smem + t * TILE_B + r0i * RSTRIDE + ch * 16) = v0;
            *(uint4*)(smem + t * TILE_B + (r0i + 64) * RSTRIDE + ch * 16) = v1;
        }
    }
    __syncthreads();

    for (int kc = 0; kc < 32; kc++) {
        const int s = kc & 1;
        const bool has = (kc + 1) < 32;

        // prefetch next chunk into registers
        uint4 pf[4][2];
        if (has) {
            const size_t koff = (size_t)(kc + 1) * 32 + (size_t)ch * 8;
#pragma unroll
            for (int t = 0; t < 4; t++) {
                pf[t][0] = *(const uint4*)(gptr[t] + (size_t)r0i * HID + koff);
                pf[t][1] = *(const uint4*)(gptr[t] + (size_t)(r0i + 64) * HID + koff);
            }
        }

        // compute on stage s
        const uint32_t base = sbase + s * STAGE_B;
        const uint32_t aAhi = base;
        const uint32_t aAlo = base + TILE_B;
        const uint32_t aBhi = base + 2 * TILE_B;
        const uint32_t aBlo = base + 3 * TILE_B;

#pragma unroll
        for (int ks = 0; ks < 2; ks++) {
            const uint32_t kb = ks * 32;

            uint32_t ah[4][4], al[4][4];
#pragma unroll
            for (int mf = 0; mf < 4; mf++) {
                uint32_t ro = (uint32_t)((wm * 64 + mf * 16) * RSTRIDE) + kb;
                ldm4(ah[mf], aAhi + ro + aoff);
                ldm4(al[mf], aAlo + ro + aoff);
            }
            uint32_t bh[2][4], bl[2][4];
#pragma unroll
            for (int p = 0; p < 2; p++) {
                uint32_t ro = (uint32_t)((wn * 32 + p * 16) * RSTRIDE) + kb;
                ldm4(bh[p], aBhi + ro + boff);
                ldm4(bl[p], aBlo + ro + boff);
            }

#pragma unroll
            for (int mf = 0; mf < 4; mf++) {
#pragma unroll
                for (int nf = 0; nf < 4; nf++) {
                    const int p = nf >> 1, q = nf & 1;
                    mma16816(acc[mf][nf], ah[mf], bh[p][2 * q], bh[p][2 * q + 1]);
                    mma16816(acc[mf][nf], ah[mf], bl[p][2 * q], bl[p][2 * q + 1]);
                    mma16816(acc[mf][nf], al[mf], bh[p][2 * q], bh[p][2 * q + 1]);
                }
            }
        }

        // store prefetched chunk into the other stage
        if (has) {
            char* st = smem + (s ^ 1) * STAGE_B;
#pragma unroll
            for (int t = 0; t < 4; t++) {
                *(uint4*)(st + t * TILE_B + r0i * RSTRIDE + ch * 16) = pf[t][0];
                *(uint4*)(st + t * TILE_B + (r0i + 64) * RSTRIDE + ch * 16) = pf[t][1];
            }
        }
        __syncthreads();
    }

    // epilogue: d0,d1 -> row g, cols 2t..2t+1 ; d2,d3 -> row g+8
    const int g = lane >> 2;
    const int t2 = (lane & 3) * 2;
#pragma unroll
    for (int mf = 0; mf < 4; mf++) {
        const int row0 = brow + wm * 64 + mf * 16 + g;
#pragma unroll
        for (int nf = 0; nf < 4; nf++) {
            const int col = bcol + wn * 32 + nf * 8 + t2;
            float2 bv = *(const float2*)(bias + col);
            float2 o0 = make_float2(acc[mf][nf][0] + bv.x, acc[mf][nf][1] + bv.y);
            float2 o1 = make_float2(acc[mf][nf][2] + bv.x, acc[mf][nf][3] + bv.y);
            *(float2*)(Y + (size_t)row0 * HID + col)       = o0;
            *(float2*)(Y + (size_t)(row0 + 8) * HID + col) = o1;
        }
    }
}

// ============================================================================
// RoPE: inv-freq (double-precision match), table at (SEQ x 512), apply.
// Reference quirk reproduced: cos/sin OF [sin t, cos t]; V also roped.
// ============================================================================
__global__ void make_invf_kernel() {
    int j = threadIdx.x;
    if (j < HID / 2) {
        double e = exp(-((double)(2 * j) / (double)HID) * log(10000.0));
        g_invf[j] = (float)e;
    }
}

__global__ __launch_bounds__(256) void rope_table_kernel() {
    int idx = blockIdx.x * 256 + threadIdx.x;   // SEQ*512 threads
    int s = idx >> 9;
    int j = idx & 511;
    float t = (float)s * g_invf[j];
    float st, ct;
    sincosf(t, &st, &ct);
    float s1, c1, s2, c2;
    sincosf(st, &s1, &c1);
    sincosf(ct, &s2, &c2);
    g_tab[idx] = make_float4(c1, s1, c2, s2);
}

__global__ __launch_bounds__(256) void rope_apply_kernel() {
    int idx = blockIdx.x * 256 + threadIdx.x;   // MROWS*512 threads
    int row = idx >> 9;
    int j   = idx & 511;
    int s   = row & (SEQ - 1);

    float4 t = g_tab[(s << 9) | j];   // c1, s1, c2, s2
    size_t i1 = (size_t)row * HID + j;
    size_t i2 = i1 + 512;
    {
        float x1 = g_Q[i1], x2 = g_Q[i2];
        g_Q[i1] = x1 * t.x + x2 * t.y;
        g_Q[i2] = x2 * t.z - x1 * t.w;
    }
    {
        float x1 = g_K[i1], x2 = g_K[i2];
        g_K[i1] = x1 * t.x + x2 * t.y;
        g_K[i2] = x2 * t.z - x1 * t.w;
    }
    {
        float x1 = g_V[i1], x2 = g_V[i2];
        g_V[i1] = x1 * t.x + x2 * t.y;
        g_V[i2] = x2 * t.z - x1 * t.w;
    }
}

// ============================================================================
// Flash attention (f32x2 core); epilogue writes bf16 hi/lo split context
// directly into g_Ahi/g_Alo for the final mma projection.
// ============================================================================
__global__ __launch_bounds__(64) void attn_kernel() {
    __shared__ float Ks[64][64];
    __shared__ float Vs[64][64];
    __shared__ float Ss[64][64];

    const int tid = threadIdx.x;
    const int qt  = blockIdx.x;
    const int bh  = blockIdx.y;
    const int b   = bh >> 4;
    const int hd  = bh & 15;
    const int base_row = b * SEQ;
    const int qrow = base_row + qt * 64 + tid;

    const float* qptr = g_Q + (size_t)qrow * HID + hd * HD;

    unsigned long long q2[32];
#pragma unroll
    for (int i = 0; i < 16; i++) {
        ulonglong2 v = ((const ulonglong2*)qptr)[i];
        q2[2 * i] = v.x; q2[2 * i + 1] = v.y;
    }
    unsigned long long o2[32];
#pragma unroll
    for (int i = 0; i < 32; i++) o2[i] = 0ULL;

    float m = -1e30f, l = 0.0f;

    for (int kt = 0; kt < 16; kt++) {
        __syncthreads();
        const float* kbase = g_K + (size_t)(base_row + kt * 64) * HID + hd * HD;
        const float* vbase = g_V + (size_t)(base_row + kt * 64) * HID + hd * HD;
#pragma unroll
        for (int i = 0; i < 16; i++) {
            int idx = i * 64 + tid;
            int rr = idx >> 4, c4 = idx & 15;
            ((float4*)Ks)[idx] = *(const float4*)(kbase + (size_t)rr * HID + c4 * 4);
            ((float4*)Vs)[idx] = *(const float4*)(vbase + (size_t)rr * HID + c4 * 4);
        }
        __syncthreads();

        float tmax = -1e30f;
#pragma unroll 4
        for (int kk = 0; kk < 64; kk++) {
            const ulonglong2* kp = (const ulonglong2*)&Ks[kk][0];
            unsigned long long sa = 0ULL, sb = 0ULL, sc = 0ULL, sd = 0ULL;
#pragma unroll
            for (int i = 0; i < 8; i++) {
                ulonglong2 k0 = kp[2 * i];
                ulonglong2 k1 = kp[2 * i + 1];
                f2fma(sa, q2[4 * i + 0], k0.x);
                f2fma(sb, q2[4 * i + 1], k0.y);
                f2fma(sc, q2[4 * i + 2], k1.x);
                f2fma(sd, q2[4 * i + 3], k1.y);
            }
            f2add(sa, sa, sb);
            f2add(sc, sc, sd);
            f2add(sa, sa, sc);
            float2 sv = f2unpack(sa);
            float sval = (sv.x + sv.y) * 0.125f;
            Ss[kk][tid] = sval;
            tmax = fmaxf(tmax, sval);
        }

        float mnew = fmaxf(m, tmax);
        float corr = __expf(m - mnew);
        l *= corr;
        unsigned long long corr2 = f2pack(corr, corr);
#pragma unroll
        for (int i = 0; i < 32; i++) f2mul(o2[i], o2[i], corr2);

#pragma unroll 2
        for (int kk = 0; kk < 64; kk++) {
            float p = __expf(Ss[kk][tid] - mnew);
            l += p;
            unsigned long long p2 = f2pack(p, p);
            const ulonglong2* vp = (const ulonglong2*)&Vs[kk][0];
#pragma unroll
            for (int i = 0; i < 16; i++) {
                ulonglong2 vv = vp[i];
                f2fma(o2[2 * i],     p2, vv.x);
                f2fma(o2[2 * i + 1], p2, vv.y);
            }
        }
        m = mnew;
    }

    float inv = 1.0f / l;
    unsigned long long inv2 = f2pack(inv, inv);
#pragma unroll
    for (int i = 0; i < 32; i++) f2mul(o2[i], o2[i], inv2);

    __nv_bfloat162* chp = (__nv_bfloat162*)(g_Ahi + (size_t)qrow * HID + hd * HD);
    __nv_bfloat162* clp = (__nv_bfloat162*)(g_Alo + (size_t)qrow * HID + hd * HD);
#pragma unroll
    for (int i = 0; i < 32; i++) {
        float2 f = f2unpack(o2[i]);
        __nv_bfloat162 hh = __floats2bfloat162_rn(f.x, f.y);
        float2 fb = __bfloat1622float2(hh);
        __nv_bfloat162 ll = __floats2bfloat162_rn(f.x - fb.x, f.y - fb.y);
        chp[i] = hh;
        clp[i] = ll;
    }
}

// ============================================================================
// launch
// ============================================================================
extern "C" void kernel_launch(void* const* d_in, const int* in_sizes, int n_in,
                              void* d_out, int out_size) {
    (void)in_sizes; (void)n_in; (void)out_size;
    const float* query = (const float*)d_in[0];
    const float* key   = (const float*)d_in[1];
    const float* value = (const float*)d_in[2];
    const float* Wq    = (const float*)d_in[3];
    const float* bq    = (const float*)d_in[4];
    const float* Wk    = (const float*)d_in[5];
    const float* bk    = (const float*)d_in[6];
    const float* Wv    = (const float*)d_in[7];
    const float* bv    = (const float*)d_in[8];
    const float* Wo    = (const float*)d_in[9];
    const float* bo    = (const float*)d_in[10];
    float* out = (float*)d_out;

    float *Qp, *Kp, *Vp;
    __nv_bfloat16 *Ahi, *Alo, *Bhi, *Blo;
    cudaGetSymbolAddress((void**)&Qp, g_Q);
    cudaGetSymbolAddress((void**)&Kp, g_K);
    cudaGetSymbolAddress((void**)&Vp, g_V);
    cudaGetSymbolAddress((void**)&Ahi, g_Ahi);
    cudaGetSymbolAddress((void**)&Alo, g_Alo);
    cudaGetSymbolAddress((void**)&Bhi, g_Bhi);
    cudaGetSymbolAddress((void**)&Blo, g_Blo);

    cudaFuncSetAttribute(gemm_mma, cudaFuncAttributeMaxDynamicSharedMemorySize, GEMM_SMEM);

    const int act4 = MROWS * HID / 4;   // 2M float4
    const int w4   = HID * HID / 4;     // 256K float4
    dim3 ggrid(HID / 128, MROWS / 128); // (8, 64)

    make_invf_kernel<<<1, 512>>>();
    rope_table_kernel<<<(SEQ * 512) / 256, 256>>>();

    split_bf16_kernel<<<act4 / 256, 256>>>(query, Ahi, Alo, act4);
    split_bf16_kernel<<<w4 / 256, 256>>>(Wq, Bhi, Blo, w4);
    gemm_mma<<<ggrid, 256, GEMM_SMEM>>>(Ahi, Alo, Bhi, Blo, bq, Qp);

    split_bf16_kernel<<<act4 / 256, 256>>>(key, Ahi, Alo, act4);
    split_bf16_kernel<<<w4 / 256, 256>>>(Wk, Bhi, Blo, w4);
    gemm_mma<<<ggrid, 256, GEMM_SMEM>>>(Ahi, Alo, Bhi, Blo, bk, Kp);

    split_bf16_kernel<<<act4 / 256, 256>>>(value, Ahi, Alo, act4);
    split_bf16_kernel<<<w4 / 256, 256>>>(Wv, Bhi, Blo, w4);
    gemm_mma<<<ggrid, 256, GEMM_SMEM>>>(Ahi, Alo, Bhi, Blo, bv, Vp);

    rope_apply_kernel<<<(MROWS * 512) / 256, 256>>>();

    attn_kernel<<<dim3(16, 128), 64>>>();   // writes bf16 split ctx -> Ahi/Alo

    split_bf16_kernel<<<w4 / 256, 256>>>(Wo, Bhi, Blo, w4);
    gemm_mma<<<ggrid, 256, GEMM_SMEM>>>(Ahi, Alo, Bhi, Blo, bo, out);
}

// round 5
// speedup vs baseline: 2.6780x; 1.8000x over previous
#include <cuda_runtime.h>
#include <cuda_bf16.h>
#include <cstdint>

#define HID 1024
#define HEADS 16
#define HD 64
#define BATCH 8
#define SEQ 1024
#define MROWS (BATCH * SEQ)

// ---------------- scratch (device globals; no allocation allowed) ----------
__device__ float g_Q[MROWS * HID];
__device__ float g_K[MROWS * HID];
__device__ float g_V[MROWS * HID];
__device__ __nv_bfloat16 g_Qh[MROWS * HID];
__device__ __nv_bfloat16 g_Ql[MROWS * HID];
__device__ __nv_bfloat16 g_Kh[MROWS * HID];
__device__ __nv_bfloat16 g_Kl[MROWS * HID];
__device__ __nv_bfloat16 g_Vh[MROWS * HID];
__device__ __nv_bfloat16 g_Vl[MROWS * HID];
__device__ __nv_bfloat16 g_Ahi[MROWS * HID];
__device__ __nv_bfloat16 g_Alo[MROWS * HID];
__device__ __nv_bfloat16 g_Bhi[HID * HID];
__device__ __nv_bfloat16 g_Blo[HID * HID];
__device__ float g_invf[HID / 2];
__device__ float4 g_tab[SEQ * (HID / 2)];

// ---------------- helpers ----------------------------------------
__device__ __forceinline__ uint32_t smem_u32(const void* p) {
    uint32_t a;
    asm("{ .reg .u64 t; cvta.to.shared.u64 t, %1; cvt.u32.u64 %0, t; }"
        : "=r"(a) : "l"(p));
    return a;
}
__device__ __forceinline__ void ldm4(uint32_t* r, uint32_t addr) {
    asm volatile("ldmatrix.sync.aligned.m8n8.x4.shared.b16 {%0,%1,%2,%3}, [%4];"
                 : "=r"(r[0]), "=r"(r[1]), "=r"(r[2]), "=r"(r[3]) : "r"(addr));
}
__device__ __forceinline__ void ldm4t(uint32_t* r, uint32_t addr) {
    asm volatile("ldmatrix.sync.aligned.m8n8.x4.trans.shared.b16 {%0,%1,%2,%3}, [%4];"
                 : "=r"(r[0]), "=r"(r[1]), "=r"(r[2]), "=r"(r[3]) : "r"(addr));
}
__device__ __forceinline__ void mma16816(float* d, const uint32_t* a,
                                         uint32_t b0, uint32_t b1) {
    asm volatile(
        "mma.sync.aligned.m16n8k16.row.col.f32.bf16.bf16.f32 "
        "{%0,%1,%2,%3}, {%4,%5,%6,%7}, {%8,%9}, {%0,%1,%2,%3};"
        : "+f"(d[0]), "+f"(d[1]), "+f"(d[2]), "+f"(d[3])
        : "r"(a[0]), "r"(a[1]), "r"(a[2]), "r"(a[3]), "r"(b0), "r"(b1));
}
// split pair of floats into bf16x2 hi + bf16x2 lo (packed u32 each)
__device__ __forceinline__ void split2(float x, float y, uint32_t& hi, uint32_t& lo) {
    __nv_bfloat162 h = __floats2bfloat162_rn(x, y);
    float2 f = __bfloat1622float2(h);
    __nv_bfloat162 l2 = __floats2bfloat162_rn(x - f.x, y - f.y);
    hi = *reinterpret_cast<uint32_t*>(&h);
    lo = *reinterpret_cast<uint32_t*>(&l2);
}

// ============================================================================
// fp32 -> bf16 split (hi + lo). n4 = elements/4.
// ============================================================================
__global__ __launch_bounds__(256) void split_bf16_kernel(
    const float* __restrict__ src, __nv_bfloat16* __restrict__ hi,
    __nv_bfloat16* __restrict__ lo, int n4)
{
    int idx = blockIdx.x * 256 + threadIdx.x;
    if (idx >= n4) return;
    float4 v = ((const float4*)src)[idx];
    __nv_bfloat162 h01 = __floats2bfloat162_rn(v.x, v.y);
    __nv_bfloat162 h23 = __floats2bfloat162_rn(v.z, v.w);
    float2 f01 = __bfloat1622float2(h01);
    float2 f23 = __bfloat1622float2(h23);
    __nv_bfloat162 l01 = __floats2bfloat162_rn(v.x - f01.x, v.y - f01.y);
    __nv_bfloat162 l23 = __floats2bfloat162_rn(v.z - f23.x, v.w - f23.y);
    ((__nv_bfloat162*)hi)[2 * idx]     = h01;
    ((__nv_bfloat162*)hi)[2 * idx + 1] = h23;
    ((__nv_bfloat162*)lo)[2 * idx]     = l01;
    ((__nv_bfloat162*)lo)[2 * idx + 1] = l23;
}

// ============================================================================
// mma.sync bf16 GEMM (NT): Y = X*W^T + bias, 3-term split emulation.
// CTA 128x128, warp 64x32, K-chunk 32, double-buffered smem (80B row stride).
// ============================================================================
#define RSTRIDE 80
#define TILE_B (128 * RSTRIDE)
#define STAGE_B (4 * TILE_B)
#define GEMM_SMEM (2 * STAGE_B)

__global__ __launch_bounds__(256, 1)
void gemm_mma(const __nv_bfloat16* __restrict__ Ahi, const __nv_bfloat16* __restrict__ Alo,
              const __nv_bfloat16* __restrict__ Bhi, const __nv_bfloat16* __restrict__ Blo,
              const float* __restrict__ bias, float* __restrict__ Y)
{
    extern __shared__ __align__(128) char smem[];

    const int tid  = threadIdx.x;
    const int wid  = tid >> 5;
    const int lane = tid & 31;
    const int wm   = wid & 1;
    const int wn   = wid >> 1;
    const int brow = blockIdx.y * 128;
    const int bcol = blockIdx.x * 128;

    const uint32_t sbase = smem_u32(smem);

    const uint32_t aoff = (uint32_t)(((lane & 7) + ((lane >> 3) & 1) * 8) * RSTRIDE
                                     + ((lane >> 4) & 1) * 16);
    const uint32_t boff = (uint32_t)(((lane & 7) + ((lane >> 4) & 1) * 8) * RSTRIDE
                                     + ((lane >> 3) & 1) * 16);

    const int r0i = tid >> 2;
    const int ch  = tid & 3;

    const __nv_bfloat16* gptr[4];
    gptr[0] = Ahi + (size_t)brow * HID;
    gptr[1] = Alo + (size_t)brow * HID;
    gptr[2] = Bhi + (size_t)bcol * HID;
    gptr[3] = Blo + (size_t)bcol * HID;

    float acc[4][4][4];
#pragma unroll
    for (int i = 0; i < 4; i++)
#pragma unroll
        for (int j = 0; j < 4; j++)
#pragma unroll
            for (int r = 0; r < 4; r++) acc[i][j][r] = 0.0f;

    {
        const size_t koff = (size_t)ch * 8;
#pragma unroll
        for (int t = 0; t < 4; t++) {
            uint4 v0 = *(const uint4*)(gptr[t] + (size_t)r0i * HID + koff);
            uint4 v1 = *(const uint4*)(gptr[t] + (size_t)(r0i + 64) * HID + koff);
            *(uint4*)(smem + t * TILE_B + r0i * RSTRIDE + ch * 16) = v0;
            *(uint4*)(smem + t * TILE_B + (r0i + 64) * RSTRIDE + ch * 16) = v1;
        }
    }
    __syncthreads();

    for (int kc = 0; kc < 32; kc++) {
        const int s = kc & 1;
        const bool has = (kc + 1) < 32;

        uint4 pf[4][2];
        if (has) {
            const size_t koff = (size_t)(kc + 1) * 32 + (size_t)ch * 8;
#pragma unroll
            for (int t = 0; t < 4; t++) {
                pf[t][0] = *(const uint4*)(gptr[t] + (size_t)r0i * HID + koff);
                pf[t][1] = *(const uint4*)(gptr[t] + (size_t)(r0i + 64) * HID + koff);
            }
        }

        const uint32_t base = sbase + s * STAGE_B;
        const uint32_t aAhi = base;
        const uint32_t aAlo = base + TILE_B;
        const uint32_t aBhi = base + 2 * TILE_B;
        const uint32_t aBlo = base + 3 * TILE_B;

#pragma unroll
        for (int ks = 0; ks < 2; ks++) {
            const uint32_t kb = ks * 32;

            uint32_t ah[4][4], al[4][4];
#pragma unroll
            for (int mf = 0; mf < 4; mf++) {
                uint32_t ro = (uint32_t)((wm * 64 + mf * 16) * RSTRIDE) + kb;
                ldm4(ah[mf], aAhi + ro + aoff);
                ldm4(al[mf], aAlo + ro + aoff);
            }
            uint32_t bh[2][4], bl[2][4];
#pragma unroll
            for (int p = 0; p < 2; p++) {
                uint32_t ro = (uint32_t)((wn * 32 + p * 16) * RSTRIDE) + kb;
                ldm4(bh[p], aBhi + ro + boff);
                ldm4(bl[p], aBlo + ro + boff);
            }

#pragma unroll
            for (int mf = 0; mf < 4; mf++) {
#pragma unroll
                for (int nf = 0; nf < 4; nf++) {
                    const int p = nf >> 1, q = nf & 1;
                    mma16816(acc[mf][nf], ah[mf], bh[p][2 * q], bh[p][2 * q + 1]);
                    mma16816(acc[mf][nf], ah[mf], bl[p][2 * q], bl[p][2 * q + 1]);
                    mma16816(acc[mf][nf], al[mf], bh[p][2 * q], bh[p][2 * q + 1]);
                }
            }
        }

        if (has) {
            char* st = smem + (s ^ 1) * STAGE_B;
#pragma unroll
            for (int t = 0; t < 4; t++) {
                *(uint4*)(st + t * TILE_B + r0i * RSTRIDE + ch * 16) = pf[t][0];
                *(uint4*)(st + t * TILE_B + (r0i + 64) * RSTRIDE + ch * 16) = pf[t][1];
            }
        }
        __syncthreads();
    }

    const int g = lane >> 2;
    const int t2 = (lane & 3) * 2;
#pragma unroll
    for (int mf = 0; mf < 4; mf++) {
        const int row0 = brow + wm * 64 + mf * 16 + g;
#pragma unroll
        for (int nf = 0; nf < 4; nf++) {
            const int col = bcol + wn * 32 + nf * 8 + t2;
            float2 bv = *(const float2*)(bias + col);
            float2 o0 = make_float2(acc[mf][nf][0] + bv.x, acc[mf][nf][1] + bv.y);
            float2 o1 = make_float2(acc[mf][nf][2] + bv.x, acc[mf][nf][3] + bv.y);
            *(float2*)(Y + (size_t)row0 * HID + col)       = o0;
            *(float2*)(Y + (size_t)(row0 + 8) * HID + col) = o1;
        }
    }
}

// ============================================================================
// RoPE: table build, then apply + emit bf16 hi/lo splits of roped Q,K,V.
// Q prescaled by 0.125 (exact) so attention scores come out pre-scaled.
// ============================================================================
__global__ void make_invf_kernel() {
    int j = threadIdx.x;
    if (j < HID / 2) {
        double e = exp(-((double)(2 * j) / (double)HID) * log(10000.0));
        g_invf[j] = (float)e;
    }
}

__global__ __launch_bounds__(256) void rope_table_kernel() {
    int idx = blockIdx.x * 256 + threadIdx.x;
    int s = idx >> 9;
    int j = idx & 511;
    float t = (float)s * g_invf[j];
    float st, ct;
    sincosf(t, &st, &ct);
    float s1, c1, s2, c2;
    sincosf(st, &s1, &c1);
    sincosf(ct, &s2, &c2);
    g_tab[idx] = make_float4(c1, s1, c2, s2);
}

__device__ __forceinline__ void split1(float x, __nv_bfloat16& h, __nv_bfloat16& l) {
    h = __float2bfloat16_rn(x);
    l = __float2bfloat16_rn(x - __bfloat162float(h));
}

__global__ __launch_bounds__(256) void rope_split_kernel() {
    int idx = blockIdx.x * 256 + threadIdx.x;   // MROWS*512
    int row = idx >> 9;
    int j   = idx & 511;
    int s   = row & (SEQ - 1);

    float4 t = g_tab[(s << 9) | j];
    size_t i1 = (size_t)row * HID + j;
    size_t i2 = i1 + 512;
    {
        float x1 = g_Q[i1], x2 = g_Q[i2];
        float y1 = (x1 * t.x + x2 * t.y) * 0.125f;
        float y2 = (x2 * t.z - x1 * t.w) * 0.125f;
        split1(y1, g_Qh[i1], g_Ql[i1]);
        split1(y2, g_Qh[i2], g_Ql[i2]);
    }
    {
        float x1 = g_K[i1], x2 = g_K[i2];
        float y1 = x1 * t.x + x2 * t.y;
        float y2 = x2 * t.z - x1 * t.w;
        split1(y1, g_Kh[i1], g_Kl[i1]);
        split1(y2, g_Kh[i2], g_Kl[i2]);
    }
    {
        float x1 = g_V[i1], x2 = g_V[i2];
        float y1 = x1 * t.x + x2 * t.y;
        float y2 = x2 * t.z - x1 * t.w;
        split1(y1, g_Vh[i1], g_Vl[i1]);
        split1(y2, g_Vh[i2], g_Vl[i2]);
    }
}

// ============================================================================
// Tensor-core flash attention. Block = 128 q-rows x one (b,h); 8 warps x m16.
// Scores & P.V via mma.sync with 3-term bf16-split; online softmax in frags.
// smem rows 144B stride (conflict-free ldmatrix). Ctx written as bf16 splits.
// ============================================================================
#define AST 144                       // bytes per 64-dim row in attn smem
#define AQ_H 0
#define AQ_L (128 * AST)              // 18432
#define AK_H (2 * 128 * AST)          // 36864
#define AK_L (AK_H + 64 * AST)        // 46080
#define AV_H (AK_H + 2 * 64 * AST)    // 55296
#define AV_L (AK_H + 3 * 64 * AST)    // 64512
#define ATTN_SMEM (AK_H + 4 * 64 * AST)  // 73728

__global__ __launch_bounds__(256, 2) void attn_mma() {
    extern __shared__ __align__(128) char smem[];

    const int tid  = threadIdx.x;
    const int wid  = tid >> 5;
    const int lane = tid & 31;
    const int qt   = blockIdx.x;          // 8 q-tiles
    const int bh   = blockIdx.y;          // 128
    const int b    = bh >> 4;
    const int h    = bh & 15;
    const int qbase = b * SEQ + qt * 128;
    const size_t colbase = (size_t)h * HD;

    const uint32_t sb = smem_u32(smem);

    // ldmatrix lane offsets (within a tile region)
    const uint32_t aoff = (uint32_t)(((lane & 7) + ((lane >> 3) & 1) * 8) * AST
                                     + ((lane >> 4) & 1) * 16);   // A non-trans
    const uint32_t boff = (uint32_t)(((lane & 7) + ((lane >> 4) & 1) * 8) * AST
                                     + ((lane >> 3) & 1) * 16);   // B non-trans (K)
    const uint32_t voff = (uint32_t)(((lane & 7) + ((lane >> 3) & 1) * 8) * AST
                                     + ((lane >> 4) & 1) * 16);   // B trans (V)

    // load Q tile (hi+lo): 128 rows x 8 chunks of 16B per array
#pragma unroll
    for (int i = 0; i < 4; i++) {
        int chunk = tid + 256 * i;
        int r = chunk >> 3, c = chunk & 7;
        size_t go = (size_t)(qbase + r) * HID + colbase + c * 8;
        *(uint4*)(smem + AQ_H + r * AST + c * 16) = *(const uint4*)(g_Qh + go);
        *(uint4*)(smem + AQ_L + r * AST + c * 16) = *(const uint4*)(g_Ql + go);
    }

    float o[8][4];
#pragma unroll
    for (int nf = 0; nf < 8; nf++)
#pragma unroll
        for (int r = 0; r < 4; r++) o[nf][r] = 0.0f;
    float m0 = -1e30f, m1 = -1e30f, l0 = 0.0f, l1 = 0.0f;

    const uint32_t qrow_off = (uint32_t)(wid * 16 * AST);

    for (int kt = 0; kt < 16; kt++) {
        __syncthreads();
        // load K/V tiles (hi+lo): 64 rows x 8 chunks x 4 arrays = 2048 uint4
        const int krow0 = b * SEQ + kt * 64;
#pragma unroll
        for (int i = 0; i < 8; i++) {
            int idx = tid + 256 * i;
            int arr = idx >> 9;
            int rem = idx & 511;
            int r = rem >> 3, c = rem & 7;
            size_t go = (size_t)(krow0 + r) * HID + colbase + c * 8;
            const __nv_bfloat16* src = (arr == 0) ? g_Kh : (arr == 1) ? g_Kl
                                    : (arr == 2) ? g_Vh : g_Vl;
            *(uint4*)(smem + AK_H + arr * (64 * AST) + r * AST + c * 16) =
                *(const uint4*)(src + go);
        }
        __syncthreads();

        // ---- scores: S = (Qh+Ql)(Kh+Kl)^T, 3 terms ----
        float sfr[8][4];
#pragma unroll
        for (int nf = 0; nf < 8; nf++)
#pragma unroll
            for (int r = 0; r < 4; r++) sfr[nf][r] = 0.0f;

#pragma unroll
        for (int kq = 0; kq < 4; kq++) {
            uint32_t qh[4], ql[4];
            ldm4(qh, sb + AQ_H + qrow_off + kq * 32 + aoff);
            ldm4(ql, sb + AQ_L + qrow_off + kq * 32 + aoff);
            uint32_t kh[4][4], kl[4][4];
#pragma unroll
            for (int p = 0; p < 4; p++) {
                ldm4(kh[p], sb + AK_H + (uint32_t)(p * 16 * AST) + kq * 32 + boff);
                ldm4(kl[p], sb + AK_L + (uint32_t)(p * 16 * AST) + kq * 32 + boff);
            }
#pragma unroll
            for (int nf = 0; nf < 8; nf++) {
                const int p = nf >> 1, q = nf & 1;
                mma16816(sfr[nf], qh, kh[p][2 * q], kh[p][2 * q + 1]);
                mma16816(sfr[nf], qh, kl[p][2 * q], kl[p][2 * q + 1]);
                mma16816(sfr[nf], ql, kh[p][2 * q], kh[p][2 * q + 1]);
            }
        }

        // ---- online softmax ----
        float mx0 = -1e30f, mx1 = -1e30f;
#pragma unroll
        for (int nf = 0; nf < 8; nf++) {
            mx0 = fmaxf(mx0, fmaxf(sfr[nf][0], sfr[nf][1]));
            mx1 = fmaxf(mx1, fmaxf(sfr[nf][2], sfr[nf][3]));
        }
        mx0 = fmaxf(mx0, __shfl_xor_sync(0xFFFFFFFF, mx0, 1));
        mx0 = fmaxf(mx0, __shfl_xor_sync(0xFFFFFFFF, mx0, 2));
        mx1 = fmaxf(mx1, __shfl_xor_sync(0xFFFFFFFF, mx1, 1));
        mx1 = fmaxf(mx1, __shfl_xor_sync(0xFFFFFFFF, mx1, 2));

        float mn0 = fmaxf(m0, mx0), mn1 = fmaxf(m1, mx1);
        float c0 = __expf(m0 - mn0), c1 = __expf(m1 - mn1);
        l0 *= c0; l1 *= c1;
#pragma unroll
        for (int nf = 0; nf < 8; nf++) {
            o[nf][0] *= c0; o[nf][1] *= c0;
            o[nf][2] *= c1; o[nf][3] *= c1;
        }
#pragma unroll
        for (int nf = 0; nf < 8; nf++) {
            sfr[nf][0] = __expf(sfr[nf][0] - mn0);
            sfr[nf][1] = __expf(sfr[nf][1] - mn0);
            sfr[nf][2] = __expf(sfr[nf][2] - mn1);
            sfr[nf][3] = __expf(sfr[nf][3] - mn1);
            l0 += sfr[nf][0] + sfr[nf][1];
            l1 += sfr[nf][2] + sfr[nf][3];
        }
        m0 = mn0; m1 = mn1;

        // ---- O += (Ph+Pl)(Vh+Vl), 3 terms; P frags from score frags ----
#pragma unroll
        for (int kk = 0; kk < 4; kk++) {
            uint32_t ah[4], al[4];
            split2(sfr[2 * kk][0],     sfr[2 * kk][1],     ah[0], al[0]);
            split2(sfr[2 * kk][2],     sfr[2 * kk][3],     ah[1], al[1]);
            split2(sfr[2 * kk + 1][0], sfr[2 * kk + 1][1], ah[2], al[2]);
            split2(sfr[2 * kk + 1][2], sfr[2 * kk + 1][3], ah[3], al[3]);

            uint32_t vh[4][4], vl[4][4];
#pragma unroll
            for (int p = 0; p < 4; p++) {
                uint32_t ro = (uint32_t)(kk * 16 * AST) + (uint32_t)(p * 32);
                ldm4t(vh[p], sb + AV_H + ro + voff);
                ldm4t(vl[p], sb + AV_L + ro + voff);
            }
#pragma unroll
            for (int nf = 0; nf < 8; nf++) {
                const int p = nf >> 1, q = nf & 1;
                mma16816(o[nf], ah, vh[p][2 * q], vh[p][2 * q + 1]);
                mma16816(o[nf], ah, vl[p][2 * q], vl[p][2 * q + 1]);
                mma16816(o[nf], al, vh[p][2 * q], vh[p][2 * q + 1]);
            }
        }
    }

    // final normalize + write ctx as bf16 splits
    l0 += __shfl_xor_sync(0xFFFFFFFF, l0, 1);
    l0 += __shfl_xor_sync(0xFFFFFFFF, l0, 2);
    l1 += __shfl_xor_sync(0xFFFFFFFF, l1, 1);
    l1 += __shfl_xor_sync(0xFFFFFFFF, l1, 2);
    float inv0 = 1.0f / l0, inv1 = 1.0f / l1;

    const int g  = lane >> 2;
    const int t2 = (lane & 3) * 2;
    const int row0 = qbase + wid * 16 + g;
#pragma unroll
    for (int nf = 0; nf < 8; nf++) {
        size_t col = colbase + nf * 8 + t2;
        uint32_t hi, lo;
        split2(o[nf][0] * inv0, o[nf][1] * inv0, hi, lo);
        *(uint32_t*)(g_Ahi + (size_t)row0 * HID + col) = hi;
        *(uint32_t*)(g_Alo + (size_t)row0 * HID + col) = lo;
        split2(o[nf][2] * inv1, o[nf][3] * inv1, hi, lo);
        *(uint32_t*)(g_Ahi + (size_t)(row0 + 8) * HID + col) = hi;
        *(uint32_t*)(g_Alo + (size_t)(row0 + 8) * HID + col) = lo;
    }
}

// ============================================================================
// launch
// ============================================================================
extern "C" void kernel_launch(void* const* d_in, const int* in_sizes, int n_in,
                              void* d_out, int out_size) {
    (void)in_sizes; (void)n_in; (void)out_size;
    const float* query = (const float*)d_in[0];
    const float* key   = (const float*)d_in[1];
    const float* value = (const float*)d_in[2];
    const float* Wq    = (const float*)d_in[3];
    const float* bq    = (const float*)d_in[4];
    const float* Wk    = (const float*)d_in[5];
    const float* bk    = (const float*)d_in[6];
    const float* Wv    = (const float*)d_in[7];
    const float* bv    = (const float*)d_in[8];
    const float* Wo    = (const float*)d_in[9];
    const float* bo    = (const float*)d_in[10];
    float* out = (float*)d_out;

    float *Qp, *Kp, *Vp;
    __nv_bfloat16 *Ahi, *Alo, *Bhi, *Blo;
    cudaGetSymbolAddress((void**)&Qp, g_Q);
    cudaGetSymbolAddress((void**)&Kp, g_K);
    cudaGetSymbolAddress((void**)&Vp, g_V);
    cudaGetSymbolAddress((void**)&Ahi, g_Ahi);
    cudaGetSymbolAddress((void**)&Alo, g_Alo);
    cudaGetSymbolAddress((void**)&Bhi, g_Bhi);
    cudaGetSymbolAddress((void**)&Blo, g_Blo);

    cudaFuncSetAttribute(gemm_mma, cudaFuncAttributeMaxDynamicSharedMemorySize, GEMM_SMEM);
    cudaFuncSetAttribute(attn_mma, cudaFuncAttributeMaxDynamicSharedMemorySize, ATTN_SMEM);

    const int act4 = MROWS * HID / 4;
    const int w4   = HID * HID / 4;
    dim3 ggrid(HID / 128, MROWS / 128);

    make_invf_kernel<<<1, 512>>>();
    rope_table_kernel<<<(SEQ * 512) / 256, 256>>>();

    split_bf16_kernel<<<act4 / 256, 256>>>(query, Ahi, Alo, act4);
    split_bf16_kernel<<<w4 / 256, 256>>>(Wq, Bhi, Blo, w4);
    gemm_mma<<<ggrid, 256, GEMM_SMEM>>>(Ahi, Alo, Bhi, Blo, bq, Qp);

    split_bf16_kernel<<<act4 / 256, 256>>>(key, Ahi, Alo, act4);
    split_bf16_kernel<<<w4 / 256, 256>>>(Wk, Bhi, Blo, w4);
    gemm_mma<<<ggrid, 256, GEMM_SMEM>>>(Ahi, Alo, Bhi, Blo, bk, Kp);

    split_bf16_kernel<<<act4 / 256, 256>>>(value, Ahi, Alo, act4);
    split_bf16_kernel<<<w4 / 256, 256>>>(Wv, Bhi, Blo, w4);
    gemm_mma<<<ggrid, 256, GEMM_SMEM>>>(Ahi, Alo, Bhi, Blo, bv, Vp);

    rope_split_kernel<<<(MROWS * 512) / 256, 256>>>();

    attn_mma<<<dim3(8, 128), 256, ATTN_SMEM>>>();   // ctx splits -> Ahi/Alo

    split_bf16_kernel<<<w4 / 256, 256>>>(Wo, Bhi, Blo, w4);
    gemm_mma<<<ggrid, 256, GEMM_SMEM>>>(Ahi, Alo, Bhi, Blo, bo, out);
}

// round 6
// speedup vs baseline: 2.7911x; 1.0423x over previous
#include <cuda_runtime.h>
#include <cuda_bf16.h>
#include <cstdint>

#define HID 1024
#define HEADS 16
#define HD 64
#define BATCH 8
#define SEQ 1024
#define MROWS (BATCH * SEQ)

// ---------------- scratch (device globals; no allocation allowed) ----------
__device__ __nv_bfloat16 g_Qh[MROWS * HID];
__device__ __nv_bfloat16 g_Ql[MROWS * HID];
__device__ __nv_bfloat16 g_Kh[MROWS * HID];
__device__ __nv_bfloat16 g_Kl[MROWS * HID];
__device__ __nv_bfloat16 g_Vh[MROWS * HID];
__device__ __nv_bfloat16 g_Vl[MROWS * HID];
__device__ __nv_bfloat16 g_Ahi[MROWS * HID];
__device__ __nv_bfloat16 g_Alo[MROWS * HID];
__device__ __nv_bfloat16 g_Wqh[HID * HID];
__device__ __nv_bfloat16 g_Wql[HID * HID];
__device__ __nv_bfloat16 g_Wkh[HID * HID];
__device__ __nv_bfloat16 g_Wkl[HID * HID];
__device__ __nv_bfloat16 g_Wvh[HID * HID];
__device__ __nv_bfloat16 g_Wvl[HID * HID];
__device__ __nv_bfloat16 g_Woh[HID * HID];
__device__ __nv_bfloat16 g_Wol[HID * HID];
__device__ float g_invf[HID / 2];
__device__ float4 g_tab[SEQ * (HID / 2)];

// ---------------- helpers ----------------------------------------
__device__ __forceinline__ uint32_t smem_u32(const void* p) {
    uint32_t a;
    asm("{ .reg .u64 t; cvta.to.shared.u64 t, %1; cvt.u32.u64 %0, t; }"
        : "=r"(a) : "l"(p));
    return a;
}
__device__ __forceinline__ void ldm4(uint32_t* r, uint32_t addr) {
    asm volatile("ldmatrix.sync.aligned.m8n8.x4.shared.b16 {%0,%1,%2,%3}, [%4];"
                 : "=r"(r[0]), "=r"(r[1]), "=r"(r[2]), "=r"(r[3]) : "r"(addr));
}
__device__ __forceinline__ void ldm4t(uint32_t* r, uint32_t addr) {
    asm volatile("ldmatrix.sync.aligned.m8n8.x4.trans.shared.b16 {%0,%1,%2,%3}, [%4];"
                 : "=r"(r[0]), "=r"(r[1]), "=r"(r[2]), "=r"(r[3]) : "r"(addr));
}
__device__ __forceinline__ void mma16816(float* d, const uint32_t* a,
                                         uint32_t b0, uint32_t b1) {
    asm volatile(
        "mma.sync.aligned.m16n8k16.row.col.f32.bf16.bf16.f32 "
        "{%0,%1,%2,%3}, {%4,%5,%6,%7}, {%8,%9}, {%0,%1,%2,%3};"
        : "+f"(d[0]), "+f"(d[1]), "+f"(d[2]), "+f"(d[3])
        : "r"(a[0]), "r"(a[1]), "r"(a[2]), "r"(a[3]), "r"(b0), "r"(b1));
}
__device__ __forceinline__ void split2(float x, float y, uint32_t& hi, uint32_t& lo) {
    __nv_bfloat162 h = __floats2bfloat162_rn(x, y);
    float2 f = __bfloat1622float2(h);
    __nv_bfloat162 l2 = __floats2bfloat162_rn(x - f.x, y - f.y);
    hi = *reinterpret_cast<uint32_t*>(&h);
    lo = *reinterpret_cast<uint32_t*>(&l2);
}
// 8 fp32 -> uint4 hi + uint4 lo (8 bf16 each)
__device__ __forceinline__ void split8(const float4& u, const float4& v,
                                       uint4& hi, uint4& lo) {
    split2(u.x, u.y, hi.x, lo.x);
    split2(u.z, u.w, hi.y, lo.y);
    split2(v.x, v.y, hi.z, lo.z);
    split2(v.z, v.w, hi.w, lo.w);
}

// permutation: n' = 128p + 64s + i  ->  orig = 64p + 512s + i
__device__ __forceinline__ int perm_orig(int n) {
    int p = n >> 7, s = (n >> 6) & 1, i = n & 63;
    return 64 * p + 512 * s + i;
}

// ============================================================================
// weight prep: row-permuted bf16 split (for Wq/Wk/Wv as NT B-operand)
// ============================================================================
__global__ __launch_bounds__(256) void prep_w_rowperm(
    const float* __restrict__ W, __nv_bfloat16* __restrict__ Wh,
    __nv_bfloat16* __restrict__ Wl)
{
    int idx = blockIdx.x * 256 + threadIdx.x;   // 131072
    int n = idx >> 7;
    int c8 = (idx & 127) * 8;
    int orig = perm_orig(n);
    float4 u = *(const float4*)(W + (size_t)orig * HID + c8);
    float4 v = *(const float4*)(W + (size_t)orig * HID + c8 + 4);
    uint4 hi, lo;
    split8(u, v, hi, lo);
    *(uint4*)(Wh + (size_t)n * HID + c8) = hi;
    *(uint4*)(Wl + (size_t)n * HID + c8) = lo;
}

// weight prep: column(k)-permuted bf16 split (for Wo; ctx is permuted)
__global__ __launch_bounds__(256) void prep_w_colperm(
    const float* __restrict__ W, __nv_bfloat16* __restrict__ Wh,
    __nv_bfloat16* __restrict__ Wl)
{
    int idx = blockIdx.x * 256 + threadIdx.x;
    int n = idx >> 7;
    int k8 = (idx & 127) * 8;
    int orig = perm_orig(k8);    // contiguous over the 8-run
    float4 u = *(const float4*)(W + (size_t)n * HID + orig);
    float4 v = *(const float4*)(W + (size_t)n * HID + orig + 4);
    uint4 hi, lo;
    split8(u, v, hi, lo);
    *(uint4*)(Wh + (size_t)n * HID + k8) = hi;
    *(uint4*)(Wl + (size_t)n * HID + k8) = lo;
}

// ============================================================================
// RoPE table
// ============================================================================
__global__ void make_invf_kernel() {
    int j = threadIdx.x;
    if (j < HID / 2) {
        double e = exp(-((double)(2 * j) / (double)HID) * log(10000.0));
        g_invf[j] = (float)e;
    }
}
__global__ __launch_bounds__(256) void rope_table_kernel() {
    int idx = blockIdx.x * 256 + threadIdx.x;
    int s = idx >> 9;
    int j = idx & 511;
    float t = (float)s * g_invf[j];
    float st, ct;
    sincosf(t, &st, &ct);
    float s1, c1, s2, c2;
    sincosf(st, &s1, &c1);
    sincosf(ct, &s2, &c2);
    g_tab[idx] = make_float4(c1, s1, c2, s2);
}

// ============================================================================
// fused QKV projection: Y = X*W'^T (+bias, +RoPE, +scale) -> bf16 hi/lo.
// A = fp32 activations, converted inline; B = pre-split permuted weights.
// CTA 128x128, warp 64x32, K-chunk 32, double-buffered smem.
// ============================================================================
#define RSTRIDE 80
#define TILE_B (128 * RSTRIDE)
#define STAGE_B (4 * TILE_B)
#define GEMM_SMEM (2 * STAGE_B)    // 81920; epilogue reuses 128x132 fp32 = 67584
#define SROW 132

__global__ __launch_bounds__(256, 1)
void gemm_qkv(const float* __restrict__ X,
              const __nv_bfloat16* __restrict__ Bh_, const __nv_bfloat16* __restrict__ Bl_,
              const float* __restrict__ bias,
              __nv_bfloat16* __restrict__ outh, __nv_bfloat16* __restrict__ outl,
              float scale)
{
    extern __shared__ __align__(128) char smem[];

    const int tid  = threadIdx.x;
    const int wid  = tid >> 5;
    const int lane = tid & 31;
    const int wm   = wid & 1;
    const int wn   = wid >> 1;
    const int brow = blockIdx.y * 128;
    const int bcol = blockIdx.x * 128;

    const uint32_t sbase = smem_u32(smem);

    const uint32_t aoff = (uint32_t)(((lane & 7) + ((lane >> 3) & 1) * 8) * RSTRIDE
                                     + ((lane >> 4) & 1) * 16);
    const uint32_t boff = (uint32_t)(((lane & 7) + ((lane >> 4) & 1) * 8) * RSTRIDE
                                     + ((lane >> 3) & 1) * 16);

    const int r0i = tid >> 2;
    const int ch  = tid & 3;

    const float* Xp = X + (size_t)brow * HID;
    const __nv_bfloat16* Bhp = Bh_ + (size_t)bcol * HID;
    const __nv_bfloat16* Blp = Bl_ + (size_t)bcol * HID;

    float acc[4][4][4];
#pragma unroll
    for (int i = 0; i < 4; i++)
#pragma unroll
        for (int j = 0; j < 4; j++)
#pragma unroll
            for (int r = 0; r < 4; r++) acc[i][j][r] = 0.0f;

    // prologue: chunk 0 -> stage 0
    {
        const size_t ke = (size_t)ch * 8;
        float4 a0 = *(const float4*)(Xp + (size_t)r0i * HID + ke);
        float4 a1 = *(const float4*)(Xp + (size_t)r0i * HID + ke + 4);
        float4 a2 = *(const float4*)(Xp + (size_t)(r0i + 64) * HID + ke);
        float4 a3 = *(const float4*)(Xp + (size_t)(r0i + 64) * HID + ke + 4);
        uint4 b0 = *(const uint4*)(Bhp + (size_t)r0i * HID + ke);
        uint4 b1 = *(const uint4*)(Bhp + (size_t)(r0i + 64) * HID + ke);
        uint4 b2 = *(const uint4*)(Blp + (size_t)r0i * HID + ke);
        uint4 b3 = *(const uint4*)(Blp + (size_t)(r0i + 64) * HID + ke);
        uint4 hi, lo;
        split8(a0, a1, hi, lo);
        *(uint4*)(smem + 0 * TILE_B + r0i * RSTRIDE + ch * 16) = hi;
        *(uint4*)(smem + 1 * TILE_B + r0i * RSTRIDE + ch * 16) = lo;
        split8(a2, a3, hi, lo);
        *(uint4*)(smem + 0 * TILE_B + (r0i + 64) * RSTRIDE + ch * 16) = hi;
        *(uint4*)(smem + 1 * TILE_B + (r0i + 64) * RSTRIDE + ch * 16) = lo;
        *(uint4*)(smem + 2 * TILE_B + r0i * RSTRIDE + ch * 16) = b0;
        *(uint4*)(smem + 2 * TILE_B + (r0i + 64) * RSTRIDE + ch * 16) = b1;
        *(uint4*)(smem + 3 * TILE_B + r0i * RSTRIDE + ch * 16) = b2;
        *(uint4*)(smem + 3 * TILE_B + (r0i + 64) * RSTRIDE + ch * 16) = b3;
    }
    __syncthreads();

    for (int kc = 0; kc < 32; kc++) {
        const int s = kc & 1;
        const bool has = (kc + 1) < 32;

        float4 pa[4];
        uint4 pb[4];
        if (has) {
            const size_t ke = (size_t)(kc + 1) * 32 + (size_t)ch * 8;
            pa[0] = *(const float4*)(Xp + (size_t)r0i * HID + ke);
            pa[1] = *(const float4*)(Xp + (size_t)r0i * HID + ke + 4);
            pa[2] = *(const float4*)(Xp + (size_t)(r0i + 64) * HID + ke);
            pa[3] = *(const float4*)(Xp + (size_t)(r0i + 64) * HID + ke + 4);
            pb[0] = *(const uint4*)(Bhp + (size_t)r0i * HID + ke);
            pb[1] = *(const uint4*)(Bhp + (size_t)(r0i + 64) * HID + ke);
            pb[2] = *(const uint4*)(Blp + (size_t)r0i * HID + ke);
            pb[3] = *(const uint4*)(Blp + (size_t)(r0i + 64) * HID + ke);
        }

        const uint32_t base = sbase + s * STAGE_B;
        const uint32_t aAhi = base;
        const uint32_t aAlo = base + TILE_B;
        const uint32_t aBhi = base + 2 * TILE_B;
        const uint32_t aBlo = base + 3 * TILE_B;

#pragma unroll
        for (int ks = 0; ks < 2; ks++) {
            const uint32_t kb = ks * 32;
            uint32_t ah[4][4], al[4][4];
#pragma unroll
            for (int mf = 0; mf < 4; mf++) {
                uint32_t ro = (uint32_t)((wm * 64 + mf * 16) * RSTRIDE) + kb;
                ldm4(ah[mf], aAhi + ro + aoff);
                ldm4(al[mf], aAlo + ro + aoff);
            }
            uint32_t bh[2][4], bl[2][4];
#pragma unroll
            for (int p = 0; p < 2; p++) {
                uint32_t ro = (uint32_t)((wn * 32 + p * 16) * RSTRIDE) + kb;
                ldm4(bh[p], aBhi + ro + boff);
                ldm4(bl[p], aBlo + ro + boff);
            }
#pragma unroll
            for (int mf = 0; mf < 4; mf++) {
#pragma unroll
                for (int nf = 0; nf < 4; nf++) {
                    const int p = nf >> 1, q = nf & 1;
                    mma16816(acc[mf][nf], ah[mf], bh[p][2 * q], bh[p][2 * q + 1]);
                    mma16816(acc[mf][nf], ah[mf], bl[p][2 * q], bl[p][2 * q + 1]);
                    mma16816(acc[mf][nf], al[mf], bh[p][2 * q], bh[p][2 * q + 1]);
                }
            }
        }

        if (has) {
            char* st = smem + (s ^ 1) * STAGE_B;
            uint4 hi, lo;
            split8(pa[0], pa[1], hi, lo);
            *(uint4*)(st + 0 * TILE_B + r0i * RSTRIDE + ch * 16) = hi;
            *(uint4*)(st + 1 * TILE_B + r0i * RSTRIDE + ch * 16) = lo;
            split8(pa[2], pa[3], hi, lo);
            *(uint4*)(st + 0 * TILE_B + (r0i + 64) * RSTRIDE + ch * 16) = hi;
            *(uint4*)(st + 1 * TILE_B + (r0i + 64) * RSTRIDE + ch * 16) = lo;
            *(uint4*)(st + 2 * TILE_B + r0i * RSTRIDE + ch * 16) = pb[0];
            *(uint4*)(st + 2 * TILE_B + (r0i + 64) * RSTRIDE + ch * 16) = pb[1];
            *(uint4*)(st + 3 * TILE_B + r0i * RSTRIDE + ch * 16) = pb[2];
            *(uint4*)(st + 3 * TILE_B + (r0i + 64) * RSTRIDE + ch * 16) = pb[3];
        }
        __syncthreads();
    }

    // ---- epilogue: stage fp32 tile in smem, apply bias + RoPE + scale ----
    float* sm = (float*)smem;
    const int g  = lane >> 2;
    const int t2 = (lane & 3) * 2;
#pragma unroll
    for (int mf = 0; mf < 4; mf++) {
        const int lr = wm * 64 + mf * 16 + g;
#pragma unroll
        for (int nf = 0; nf < 4; nf++) {
            const int lc = wn * 32 + nf * 8 + t2;
            *(float2*)(sm + lr * SROW + lc)       = make_float2(acc[mf][nf][0], acc[mf][nf][1]);
            *(float2*)(sm + (lr + 8) * SROW + lc) = make_float2(acc[mf][nf][2], acc[mf][nf][3]);
        }
    }
    __syncthreads();

    const int pblk = bcol >> 7;
#pragma unroll
    for (int it = 0; it < 16; it++) {
        int idx = it * 256 + tid;
        int r  = idx >> 5;
        int c0 = (idx & 31) * 2;
        int srow = (brow + r) & (SEQ - 1);
        int j0 = 64 * pblk + c0;
        float4 t0 = g_tab[(srow << 9) | j0];
        float4 t1 = g_tab[(srow << 9) | (j0 + 1)];
        float x1a = sm[r * SROW + c0]      + bias[j0];
        float x1b = sm[r * SROW + c0 + 1]  + bias[j0 + 1];
        float x2a = sm[r * SROW + c0 + 64] + bias[j0 + 512];
        float x2b = sm[r * SROW + c0 + 65] + bias[j0 + 513];
        float y1a = (x1a * t0.x + x2a * t0.y) * scale;
        float y2a = (x2a * t0.z - x1a * t0.w) * scale;
        float y1b = (x1b * t1.x + x2b * t1.y) * scale;
        float y2b = (x2b * t1.z - x1b * t1.w) * scale;
        size_t gb = (size_t)(brow + r) * HID + bcol;
        uint32_t hi, lo;
        split2(y1a, y1b, hi, lo);
        *(uint32_t*)(outh + gb + c0) = hi;
        *(uint32_t*)(outl + gb + c0) = lo;
        split2(y2a, y2b, hi, lo);
        *(uint32_t*)(outh + gb + 64 + c0) = hi;
        *(uint32_t*)(outl + gb + 64 + c0) = lo;
    }
}

// ============================================================================
// output projection: out = Ctx*Wo'^T + bo (fp32). A,B pre-split bf16.
// ============================================================================
__global__ __launch_bounds__(256, 1)
void gemm_out(const __nv_bfloat16* __restrict__ Ahi, const __nv_bfloat16* __restrict__ Alo,
              const __nv_bfloat16* __restrict__ Bh_, const __nv_bfloat16* __restrict__ Bl_,
              const float* __restrict__ bias, float* __restrict__ Y)
{
    extern __shared__ __align__(128) char smem[];

    const int tid  = threadIdx.x;
    const int wid  = tid >> 5;
    const int lane = tid & 31;
    const int wm   = wid & 1;
    const int wn   = wid >> 1;
    const int brow = blockIdx.y * 128;
    const int bcol = blockIdx.x * 128;

    const uint32_t sbase = smem_u32(smem);
    const uint32_t aoff = (uint32_t)(((lane & 7) + ((lane >> 3) & 1) * 8) * RSTRIDE
                                     + ((lane >> 4) & 1) * 16);
    const uint32_t boff = (uint32_t)(((lane & 7) + ((lane >> 4) & 1) * 8) * RSTRIDE
                                     + ((lane >> 3) & 1) * 16);

    const int r0i = tid >> 2;
    const int ch  = tid & 3;

    const __nv_bfloat16* gptr[4];
    gptr[0] = Ahi + (size_t)brow * HID;
    gptr[1] = Alo + (size_t)brow * HID;
    gptr[2] = Bh_ + (size_t)bcol * HID;
    gptr[3] = Bl_ + (size_t)bcol * HID;

    float acc[4][4][4];
#pragma unroll
    for (int i = 0; i < 4; i++)
#pragma unroll
        for (int j = 0; j < 4; j++)
#pragma unroll
            for (int r = 0; r < 4; r++) acc[i][j][r] = 0.0f;

    {
        const size_t ke = (size_t)ch * 8;
#pragma unroll
        for (int t = 0; t < 4; t++) {
            uint4 v0 = *(const uint4*)(gptr[t] + (size_t)r0i * HID + ke);
            uint4 v1 = *(const uint4*)(gptr[t] + (size_t)(r0i + 64) * HID + ke);
            *(uint4*)(smem + t * TILE_B + r0i * RSTRIDE + ch * 16) = v0;
            *(uint4*)(smem + t * TILE_B + (r0i + 64) * RSTRIDE + ch * 16) = v1;
        }
    }
    __syncthreads();

    for (int kc = 0; kc < 32; kc++) {
        const int s = kc & 1;
        const bool has = (kc + 1) < 32;

        uint4 pf[4][2];
        if (has) {
            const size_t ke = (size_t)(kc + 1) * 32 + (size_t)ch * 8;
#pragma unroll
            for (int t = 0; t < 4; t++) {
                pf[t][0] = *(const uint4*)(gptr[t] + (size_t)r0i * HID + ke);
                pf[t][1] = *(const uint4*)(gptr[t] + (size_t)(r0i + 64) * HID + ke);
            }
        }

        const uint32_t base = sbase + s * STAGE_B;
#pragma unroll
        for (int ks = 0; ks < 2; ks++) {
            const uint32_t kb = ks * 32;
            uint32_t ah[4][4], al[4][4];
#pragma unroll
            for (int mf = 0; mf < 4; mf++) {
                uint32_t ro = (uint32_t)((wm * 64 + mf * 16) * RSTRIDE) + kb;
                ldm4(ah[mf], base + ro + aoff);
                ldm4(al[mf], base + TILE_B + ro + aoff);
            }
            uint32_t bh[2][4], bl[2][4];
#pragma unroll
            for (int p = 0; p < 2; p++) {
                uint32_t ro = (uint32_t)((wn * 32 + p * 16) * RSTRIDE) + kb;
                ldm4(bh[p], base + 2 * TILE_B + ro + boff);
                ldm4(bl[p], base + 3 * TILE_B + ro + boff);
            }
#pragma unroll
            for (int mf = 0; mf < 4; mf++) {
#pragma unroll
                for (int nf = 0; nf < 4; nf++) {
                    const int p = nf >> 1, q = nf & 1;
                    mma16816(acc[mf][nf], ah[mf], bh[p][2 * q], bh[p][2 * q + 1]);
                    mma16816(acc[mf][nf], ah[mf], bl[p][2 * q], bl[p][2 * q + 1]);
                    mma16816(acc[mf][nf], al[mf], bh[p][2 * q], bh[p][2 * q + 1]);
                }
            }
        }

        if (has) {
            char* st = smem + (s ^ 1) * STAGE_B;
#pragma unroll
            for (int t = 0; t < 4; t++) {
                *(uint4*)(st + t * TILE_B + r0i * RSTRIDE + ch * 16) = pf[t][0];
                *(uint4*)(st + t * TILE_B + (r0i + 64) * RSTRIDE + ch * 16) = pf[t][1];
            }
        }
        __syncthreads();
    }

    const int g = lane >> 2;
    const int t2 = (lane & 3) * 2;
#pragma unroll
    for (int mf = 0; mf < 4; mf++) {
        const int row0 = brow + wm * 64 + mf * 16 + g;
#pragma unroll
        for (int nf = 0; nf < 4; nf++) {
            const int col = bcol + wn * 32 + nf * 8 + t2;
            float2 bv = *(const float2*)(bias + col);
            float2 o0 = make_float2(acc[mf][nf][0] + bv.x, acc[mf][nf][1] + bv.y);
            float2 o1 = make_float2(acc[mf][nf][2] + bv.x, acc[mf][nf][3] + bv.y);
            *(float2*)(Y + (size_t)row0 * HID + col)       = o0;
            *(float2*)(Y + (size_t)(row0 + 8) * HID + col) = o1;
        }
    }
}

// ============================================================================
// tensor-core flash attention (unchanged from round 5; heads are permuted
// blocks of 64, which it is agnostic to). Writes ctx splits to g_Ahi/g_Alo.
// ============================================================================
#define AST 144
#define AQ_H 0
#define AQ_L (128 * AST)
#define AK_H (2 * 128 * AST)
#define AK_L (AK_H + 64 * AST)
#define AV_H (AK_H + 2 * 64 * AST)
#define AV_L (AK_H + 3 * 64 * AST)
#define ATTN_SMEM (AK_H + 4 * 64 * AST)

__global__ __launch_bounds__(256, 2) void attn_mma() {
    extern __shared__ __align__(128) char smem[];

    const int tid  = threadIdx.x;
    const int wid  = tid >> 5;
    const int lane = tid & 31;
    const int qt   = blockIdx.x;
    const int bh   = blockIdx.y;
    const int b    = bh >> 4;
    const int h    = bh & 15;
    const int qbase = b * SEQ + qt * 128;
    const size_t colbase = (size_t)h * HD;

    const uint32_t sb = smem_u32(smem);

    const uint32_t aoff = (uint32_t)(((lane & 7) + ((lane >> 3) & 1) * 8) * AST
                                     + ((lane >> 4) & 1) * 16);
    const uint32_t boff = (uint32_t)(((lane & 7) + ((lane >> 4) & 1) * 8) * AST
                                     + ((lane >> 3) & 1) * 16);
    const uint32_t voff = (uint32_t)(((lane & 7) + ((lane >> 3) & 1) * 8) * AST
                                     + ((lane >> 4) & 1) * 16);

#pragma unroll
    for (int i = 0; i < 4; i++) {
        int chunk = tid + 256 * i;
        int r = chunk >> 3, c = chunk & 7;
        size_t go = (size_t)(qbase + r) * HID + colbase + c * 8;
        *(uint4*)(smem + AQ_H + r * AST + c * 16) = *(const uint4*)(g_Qh + go);
        *(uint4*)(smem + AQ_L + r * AST + c * 16) = *(const uint4*)(g_Ql + go);
    }

    float o[8][4];
#pragma unroll
    for (int nf = 0; nf < 8; nf++)
#pragma unroll
        for (int r = 0; r < 4; r++) o[nf][r] = 0.0f;
    float m0 = -1e30f, m1 = -1e30f, l0 = 0.0f, l1 = 0.0f;

    const uint32_t qrow_off = (uint32_t)(wid * 16 * AST);

    for (int kt = 0; kt < 16; kt++) {
        __syncthreads();
        const int krow0 = b * SEQ + kt * 64;
#pragma unroll
        for (int i = 0; i < 8; i++) {
            int idx = tid + 256 * i;
            int arr = idx >> 9;
            int rem = idx & 511;
            int r = rem >> 3, c = rem & 7;
            size_t go = (size_t)(krow0 + r) * HID + colbase + c * 8;
            const __nv_bfloat16* src = (arr == 0) ? g_Kh : (arr == 1) ? g_Kl
                                    : (arr == 2) ? g_Vh : g_Vl;
            *(uint4*)(smem + AK_H + arr * (64 * AST) + r * AST + c * 16) =
                *(const uint4*)(src + go);
        }
        __syncthreads();

        float sfr[8][4];
#pragma unroll
        for (int nf = 0; nf < 8; nf++)
#pragma unroll
            for (int r = 0; r < 4; r++) sfr[nf][r] = 0.0f;

#pragma unroll
        for (int kq = 0; kq < 4; kq++) {
            uint32_t qh[4], ql[4];
            ldm4(qh, sb + AQ_H + qrow_off + kq * 32 + aoff);
            ldm4(ql, sb + AQ_L + qrow_off + kq * 32 + aoff);
            uint32_t kh[4][4], kl[4][4];
#pragma unroll
            for (int p = 0; p < 4; p++) {
                ldm4(kh[p], sb + AK_H + (uint32_t)(p * 16 * AST) + kq * 32 + boff);
                ldm4(kl[p], sb + AK_L + (uint32_t)(p * 16 * AST) + kq * 32 + boff);
            }
#pragma unroll
            for (int nf = 0; nf < 8; nf++) {
                const int p = nf >> 1, q = nf & 1;
                mma16816(sfr[nf], qh, kh[p][2 * q], kh[p][2 * q + 1]);
                mma16816(sfr[nf], qh, kl[p][2 * q], kl[p][2 * q + 1]);
                mma16816(sfr[nf], ql, kh[p][2 * q], kh[p][2 * q + 1]);
            }
        }

        float mx0 = -1e30f, mx1 = -1e30f;
#pragma unroll
        for (int nf = 0; nf < 8; nf++) {
            mx0 = fmaxf(mx0, fmaxf(sfr[nf][0], sfr[nf][1]));
            mx1 = fmaxf(mx1, fmaxf(sfr[nf][2], sfr[nf][3]));
        }
        mx0 = fmaxf(mx0, __shfl_xor_sync(0xFFFFFFFF, mx0, 1));
        mx0 = fmaxf(mx0, __shfl_xor_sync(0xFFFFFFFF, mx0, 2));
        mx1 = fmaxf(mx1, __shfl_xor_sync(0xFFFFFFFF, mx1, 1));
        mx1 = fmaxf(mx1, __shfl_xor_sync(0xFFFFFFFF, mx1, 2));

        float mn0 = fmaxf(m0, mx0), mn1 = fmaxf(m1, mx1);
        float c0 = __expf(m0 - mn0), c1 = __expf(m1 - mn1);
        l0 *= c0; l1 *= c1;
#pragma unroll
        for (int nf = 0; nf < 8; nf++) {
            o[nf][0] *= c0; o[nf][1] *= c0;
            o[nf][2] *= c1; o[nf][3] *= c1;
        }
#pragma unroll
        for (int nf = 0; nf < 8; nf++) {
            sfr[nf][0] = __expf(sfr[nf][0] - mn0);
            sfr[nf][1] = __expf(sfr[nf][1] - mn0);
            sfr[nf][2] = __expf(sfr[nf][2] - mn1);
            sfr[nf][3] = __expf(sfr[nf][3] - mn1);
            l0 += sfr[nf][0] + sfr[nf][1];
            l1 += sfr[nf][2] + sfr[nf][3];
        }
        m0 = mn0; m1 = mn1;

#pragma unroll
        for (int kk = 0; kk < 4; kk++) {
            uint32_t ah[4], al[4];
            split2(sfr[2 * kk][0],     sfr[2 * kk][1],     ah[0], al[0]);
            split2(sfr[2 * kk][2],     sfr[2 * kk][3],     ah[1], al[1]);
            split2(sfr[2 * kk + 1][0], sfr[2 * kk + 1][1], ah[2], al[2]);
            split2(sfr[2 * kk + 1][2], sfr[2 * kk + 1][3], ah[3], al[3]);

            uint32_t vh[4][4], vl[4][4];
#pragma unroll
            for (int p = 0; p < 4; p++) {
                uint32_t ro = (uint32_t)(kk * 16 * AST) + (uint32_t)(p * 32);
                ldm4t(vh[p], sb + AV_H + ro + voff);
                ldm4t(vl[p], sb + AV_L + ro + voff);
            }
#pragma unroll
            for (int nf = 0; nf < 8; nf++) {
                const int p = nf >> 1, q = nf & 1;
                mma16816(o[nf], ah, vh[p][2 * q], vh[p][2 * q + 1]);
                mma16816(o[nf], ah, vl[p][2 * q], vl[p][2 * q + 1]);
                mma16816(o[nf], al, vh[p][2 * q], vh[p][2 * q + 1]);
            }
        }
    }

    l0 += __shfl_xor_sync(0xFFFFFFFF, l0, 1);
    l0 += __shfl_xor_sync(0xFFFFFFFF, l0, 2);
    l1 += __shfl_xor_sync(0xFFFFFFFF, l1, 1);
    l1 += __shfl_xor_sync(0xFFFFFFFF, l1, 2);
    float inv0 = 1.0f / l0, inv1 = 1.0f / l1;

    const int g  = lane >> 2;
    const int t2 = (lane & 3) * 2;
    const int row0 = qbase + wid * 16 + g;
#pragma unroll
    for (int nf = 0; nf < 8; nf++) {
        size_t col = colbase + nf * 8 + t2;
        uint32_t hi, lo;
        split2(o[nf][0] * inv0, o[nf][1] * inv0, hi, lo);
        *(uint32_t*)(g_Ahi + (size_t)row0 * HID + col) = hi;
        *(uint32_t*)(g_Alo + (size_t)row0 * HID + col) = lo;
        split2(o[nf][2] * inv1, o[nf][3] * inv1, hi, lo);
        *(uint32_t*)(g_Ahi + (size_t)(row0 + 8) * HID + col) = hi;
        *(uint32_t*)(g_Alo + (size_t)(row0 + 8) * HID + col) = lo;
    }
}

// ============================================================================
// launch
// ============================================================================
extern "C" void kernel_launch(void* const* d_in, const int* in_sizes, int n_in,
                              void* d_out, int out_size) {
    (void)in_sizes; (void)n_in; (void)out_size;
    const float* query = (const float*)d_in[0];
    const float* key   = (const float*)d_in[1];
    const float* value = (const float*)d_in[2];
    const float* Wq    = (const float*)d_in[3];
    const float* bq    = (const float*)d_in[4];
    const float* Wk    = (const float*)d_in[5];
    const float* bk    = (const float*)d_in[6];
    const float* Wv    = (const float*)d_in[7];
    const float* bv    = (const float*)d_in[8];
    const float* Wo    = (const float*)d_in[9];
    const float* bo    = (const float*)d_in[10];
    float* out = (float*)d_out;

    __nv_bfloat16 *Qh, *Ql, *Kh, *Kl, *Vh, *Vl, *Ahi, *Alo;
    __nv_bfloat16 *Wqh, *Wql, *Wkh, *Wkl, *Wvh, *Wvl, *Woh, *Wol;
    cudaGetSymbolAddress((void**)&Qh, g_Qh);   cudaGetSymbolAddress((void**)&Ql, g_Ql);
    cudaGetSymbolAddress((void**)&Kh, g_Kh);   cudaGetSymbolAddress((void**)&Kl, g_Kl);
    cudaGetSymbolAddress((void**)&Vh, g_Vh);   cudaGetSymbolAddress((void**)&Vl, g_Vl);
    cudaGetSymbolAddress((void**)&Ahi, g_Ahi); cudaGetSymbolAddress((void**)&Alo, g_Alo);
    cudaGetSymbolAddress((void**)&Wqh, g_Wqh); cudaGetSymbolAddress((void**)&Wql, g_Wql);
    cudaGetSymbolAddress((void**)&Wkh, g_Wkh); cudaGetSymbolAddress((void**)&Wkl, g_Wkl);
    cudaGetSymbolAddress((void**)&Wvh, g_Wvh); cudaGetSymbolAddress((void**)&Wvl, g_Wvl);
    cudaGetSymbolAddress((void**)&Woh, g_Woh); cudaGetSymbolAddress((void**)&Wol, g_Wol);

    cudaFuncSetAttribute(gemm_qkv, cudaFuncAttributeMaxDynamicSharedMemorySize, GEMM_SMEM);
    cudaFuncSetAttribute(gemm_out, cudaFuncAttributeMaxDynamicSharedMemorySize, GEMM_SMEM);
    cudaFuncSetAttribute(attn_mma, cudaFuncAttributeMaxDynamicSharedMemorySize, ATTN_SMEM);

    dim3 ggrid(HID / 128, MROWS / 128);
    const int wblocks = (HID * HID / 8) / 256;   // 512

    make_invf_kernel<<<1, 512>>>();
    rope_table_kernel<<<(SEQ * 512) / 256, 256>>>();

    prep_w_rowperm<<<wblocks, 256>>>(Wq, Wqh, Wql);
    prep_w_rowperm<<<wblocks, 256>>>(Wk, Wkh, Wkl);
    prep_w_rowperm<<<wblocks, 256>>>(Wv, Wvh, Wvl);
    prep_w_colperm<<<wblocks, 256>>>(Wo, Woh, Wol);

    gemm_qkv<<<ggrid, 256, GEMM_SMEM>>>(query, Wqh, Wql, bq, Qh, Ql, 0.125f);
    gemm_qkv<<<ggrid, 256, GEMM_SMEM>>>(key,   Wkh, Wkl, bk, Kh, Kl, 1.0f);
    gemm_qkv<<<ggrid, 256, GEMM_SMEM>>>(value, Wvh, Wvl, bv, Vh, Vl, 1.0f);

    attn_mma<<<dim3(8, 128), 256, ATTN_SMEM>>>();

    gemm_out<<<ggrid, 256, GEMM_SMEM>>>(Ahi, Alo, Woh, Wol, bo, out);
}